// round 2
// baseline (speedup 1.0000x reference)
#include <cuda_runtime.h>
#include <math.h>

// ============================================================================
// BlobRegressionLoss: mean(top-k BCE) + 0.5 * soft-dice-loss, n = 9,437,184
// Exact radix-select on fp32 bit patterns (losses >= 0 so uint order == float
// order), 12/12/8-bit levels. Per-bin (count,sum) histograms let the top-k SUM
// fall out of suffix scans: no final full re-scan. Level-0 candidates are
// compacted so levels 1/2 touch only ~0.1-10% of the data.
// All per-element math is fp32 fast intrinsics; fp64 only in tiny reductions.
// ============================================================================

#define MAX_N 9437184

__device__ unsigned int g_keys[MAX_N];     // loss bit patterns
__device__ unsigned int g_cand[MAX_N];     // level-0 bin candidates
__device__ unsigned int g_h0c[4096];
__device__ float        g_h0s[4096];
__device__ unsigned int g_h1c[4096];
__device__ float        g_h1s[4096];
__device__ unsigned int g_h2c[256];
__device__ float        g_h2s[256];
__device__ float  g_sum_p, g_sum_pt, g_sum_t;
__device__ double g_above;                 // sum of losses strictly above current refinement
__device__ unsigned int g_bin0, g_bin1, g_krem, g_m;

// ---------------------------------------------------------------------------
__global__ void zero_all(unsigned int k) {
    int i = blockIdx.x * blockDim.x + threadIdx.x;
    if (i < 4096) { g_h0c[i] = 0u; g_h0s[i] = 0.0f; g_h1c[i] = 0u; g_h1s[i] = 0.0f; }
    if (i < 256)  { g_h2c[i] = 0u; g_h2s[i] = 0.0f; }
    if (i == 0) {
        g_sum_p = 0.0f; g_sum_pt = 0.0f; g_sum_t = 0.0f;
        g_above = 0.0; g_bin0 = 0u; g_bin1 = 0u; g_krem = k; g_m = 0u;
    }
}

// ---------------------------------------------------------------------------
__device__ __forceinline__ float block_reduce_f(float v, float* sh) {
    int lane = threadIdx.x & 31, wid = threadIdx.x >> 5;
    #pragma unroll
    for (int o = 16; o; o >>= 1) v += __shfl_down_sync(0xffffffffu, v, o);
    if (lane == 0) sh[wid] = v;
    __syncthreads();
    v = (threadIdx.x < (blockDim.x >> 5)) ? sh[threadIdx.x] : 0.0f;
    if (wid == 0) {
        #pragma unroll
        for (int o = 16; o; o >>= 1) v += __shfl_down_sync(0xffffffffu, v, o);
    }
    return v;
}

// Fast BCE loss + dice partials. All fp32, MUFU-based intrinsics.
__device__ __forceinline__ unsigned int loss_key(float x, float t,
                                                 float& sp, float& spt, float& st) {
    float ax = fabsf(x);
    float e  = __expf(-ax);
    float loss = fmaxf(x, 0.0f) - x * t + __logf(1.0f + e);
    float inv = __fdividef(1.0f, 1.0f + e);
    float p   = (x >= 0.0f) ? inv : (e * inv);
    sp  += p;
    spt += p * t;
    st  += t;
    return __float_as_uint(loss);
}

// ---------------------------------------------------------------------------
// Pass A: loss keys out, 12-bit high (count,sum) histogram, dice sums.
__global__ void pass_a(const float4* __restrict__ x4, const float4* __restrict__ t4,
                       const float* __restrict__ x1, const float* __restrict__ t1,
                       int n4, int n) {
    __shared__ unsigned int shc[4096];
    __shared__ float shs[4096];
    __shared__ float shr[32];
    for (int i = threadIdx.x; i < 4096; i += blockDim.x) { shc[i] = 0u; shs[i] = 0.0f; }
    __syncthreads();

    float sp = 0.0f, spt = 0.0f, st = 0.0f;
    int tid = blockIdx.x * blockDim.x + threadIdx.x;
    int stride = gridDim.x * blockDim.x;
    uint4* keys4 = reinterpret_cast<uint4*>(g_keys);

    for (int i = tid; i < n4; i += stride) {
        float4 xv = x4[i];
        float4 tv = t4[i];
        uint4 kk;
        kk.x = loss_key(xv.x, tv.x, sp, spt, st);
        kk.y = loss_key(xv.y, tv.y, sp, spt, st);
        kk.z = loss_key(xv.z, tv.z, sp, spt, st);
        kk.w = loss_key(xv.w, tv.w, sp, spt, st);
        keys4[i] = kk;
        atomicAdd(&shc[kk.x >> 20], 1u); atomicAdd(&shs[kk.x >> 20], __uint_as_float(kk.x));
        atomicAdd(&shc[kk.y >> 20], 1u); atomicAdd(&shs[kk.y >> 20], __uint_as_float(kk.y));
        atomicAdd(&shc[kk.z >> 20], 1u); atomicAdd(&shs[kk.z >> 20], __uint_as_float(kk.z));
        atomicAdd(&shc[kk.w >> 20], 1u); atomicAdd(&shs[kk.w >> 20], __uint_as_float(kk.w));
    }
    int base = n4 * 4;
    int rem = n - base;
    if (tid < rem) {
        unsigned int key = loss_key(x1[base + tid], t1[base + tid], sp, spt, st);
        g_keys[base + tid] = key;
        atomicAdd(&shc[key >> 20], 1u); atomicAdd(&shs[key >> 20], __uint_as_float(key));
    }
    __syncthreads();

    // Loss distribution populates only ~250 of 4096 bins -> flush is cheap.
    for (int i = threadIdx.x; i < 4096; i += blockDim.x) {
        unsigned int c = shc[i];
        if (c) { atomicAdd(&g_h0c[i], c); atomicAdd(&g_h0s[i], shs[i]); }
    }

    float r = block_reduce_f(sp, shr);
    if (threadIdx.x == 0) atomicAdd(&g_sum_p, r);
    __syncthreads();
    r = block_reduce_f(spt, shr);
    if (threadIdx.x == 0) atomicAdd(&g_sum_pt, r);
    __syncthreads();
    r = block_reduce_f(st, shr);
    if (threadIdx.x == 0) atomicAdd(&g_sum_t, r);
}

// ---------------------------------------------------------------------------
// 4096-bin select (levels 0 and 1): finds bin b with count(>b) < krem <= count(>=b).
// Updates g_bin{0,1}, g_krem, and g_above += sum of bins strictly above b.
template <int LEVEL>
__global__ void select12() {
    const unsigned int* cnt = (LEVEL == 0) ? g_h0c : g_h1c;
    const float* fsum       = (LEVEL == 0) ? g_h0s : g_h1s;
    __shared__ unsigned int sc[1024];
    __shared__ double ss[1024];
    __shared__ unsigned int s_krem;
    int t = threadIdx.x;
    if (t == 0) s_krem = g_krem;

    unsigned int h[4]; float hs[4];
    unsigned int local = 0; double lsum = 0.0;
    #pragma unroll
    for (int j = 0; j < 4; j++) {
        h[j] = cnt[t * 4 + j]; hs[j] = fsum[t * 4 + j];
        local += h[j]; lsum += (double)hs[j];
    }
    sc[t] = local; ss[t] = lsum;
    __syncthreads();
    unsigned int krem = s_krem;

    // inclusive suffix scan of (count, sum) over thread chunks
    for (int off = 1; off < 1024; off <<= 1) {
        unsigned int v = (t + off < 1024) ? sc[t + off] : 0u;
        double d       = (t + off < 1024) ? ss[t + off] : 0.0;
        __syncthreads();
        sc[t] += v; ss[t] += d;
        __syncthreads();
    }

    unsigned int run = sc[t] - local;  // count strictly above my chunk
    double runs = ss[t] - lsum;
    for (int j = 3; j >= 0; j--) {
        unsigned int c = h[j];
        if (run < krem && run + c >= krem) {
            if (LEVEL == 0) g_bin0 = (unsigned int)(t * 4 + j);
            else            g_bin1 = (unsigned int)(t * 4 + j);
            g_krem = krem - run;
            g_above += runs;           // single thread hits this
        }
        run += c;
        runs += (double)hs[j];
    }
}

// ---------------------------------------------------------------------------
// Pass B: compact keys in bin0 into g_cand (warp-aggregated) and build the
// 12-bit mid histogram (count,sum) over candidates.
__global__ void pass_b(int n4, int n) {
    __shared__ unsigned int shc[4096];
    __shared__ float shs[4096];
    for (int i = threadIdx.x; i < 4096; i += blockDim.x) { shc[i] = 0u; shs[i] = 0.0f; }
    __syncthreads();

    unsigned int bin0 = g_bin0;
    int lane = threadIdx.x & 31;
    int tid = blockIdx.x * blockDim.x + threadIdx.x;
    int stride = gridDim.x * blockDim.x;
    const uint4* keys4 = reinterpret_cast<const uint4*>(g_keys);

    int iters = (n4 + stride - 1) / stride;       // uniform across warp
    for (int it = 0; it < iters; it++) {
        int i = tid + it * stride;
        bool in = (i < n4);
        uint4 kk = in ? keys4[i] : make_uint4(0u, 0u, 0u, 0u);
        unsigned int ks[4] = {kk.x, kk.y, kk.z, kk.w};
        #pragma unroll
        for (int j = 0; j < 4; j++) {
            unsigned int key = ks[j];
            bool m = in && ((key >> 20) == bin0);
            unsigned int bal = __ballot_sync(0xffffffffu, m);
            int cntw = __popc(bal);
            if (cntw) {
                unsigned int basep = 0;
                int leader = __ffs(bal) - 1;
                if (lane == leader) basep = atomicAdd(&g_m, (unsigned int)cntw);
                basep = __shfl_sync(0xffffffffu, basep, leader);
                if (m) {
                    int rank = __popc(bal & ((1u << lane) - 1u));
                    g_cand[basep + rank] = key;
                    unsigned int b = (key >> 8) & 0xFFFu;
                    atomicAdd(&shc[b], 1u);
                    atomicAdd(&shs[b], __uint_as_float(key));
                }
            }
        }
    }
    // tail (n divisible by 4 in practice; keep for generality)
    int base = n4 * 4;
    int rem = n - base;
    {
        bool in = (tid < rem);
        unsigned int key = in ? g_keys[base + tid] : 0u;
        bool m = in && ((key >> 20) == bin0);
        unsigned int bal = __ballot_sync(0xffffffffu, m);
        int cntw = __popc(bal);
        if (cntw) {
            unsigned int basep = 0;
            int leader = __ffs(bal) - 1;
            if (lane == leader) basep = atomicAdd(&g_m, (unsigned int)cntw);
            basep = __shfl_sync(0xffffffffu, basep, leader);
            if (m) {
                int rank = __popc(bal & ((1u << lane) - 1u));
                g_cand[basep + rank] = key;
                unsigned int b = (key >> 8) & 0xFFFu;
                atomicAdd(&shc[b], 1u);
                atomicAdd(&shs[b], __uint_as_float(key));
            }
        }
    }
    __syncthreads();

    for (int i = threadIdx.x; i < 4096; i += blockDim.x) {
        unsigned int c = shc[i];
        if (c) { atomicAdd(&g_h1c[i], c); atomicAdd(&g_h1s[i], shs[i]); }
    }
}

// ---------------------------------------------------------------------------
// Low 8-bit histogram over candidates matching bin1.
__global__ void hist2_k() {
    __shared__ unsigned int shc[256];
    __shared__ float shs[256];
    if (threadIdx.x < 256) { shc[threadIdx.x] = 0u; shs[threadIdx.x] = 0.0f; }
    __syncthreads();

    unsigned int m = g_m;
    unsigned int bin1 = g_bin1;
    unsigned int tid = blockIdx.x * blockDim.x + threadIdx.x;
    unsigned int stride = gridDim.x * blockDim.x;
    for (unsigned int i = tid; i < m; i += stride) {
        unsigned int key = g_cand[i];
        if (((key >> 8) & 0xFFFu) == bin1) {
            atomicAdd(&shc[key & 0xFFu], 1u);
            atomicAdd(&shs[key & 0xFFu], __uint_as_float(key));
        }
    }
    __syncthreads();
    if (threadIdx.x < 256) {
        unsigned int c = shc[threadIdx.x];
        if (c) { atomicAdd(&g_h2c[threadIdx.x], c); atomicAdd(&g_h2s[threadIdx.x], shs[threadIdx.x]); }
    }
}

// ---------------------------------------------------------------------------
// Final 256-bin select + finalize: exact pivot, tie correction, dice combine.
__global__ void select_final(float* out, int k) {
    __shared__ unsigned int sc[256];
    __shared__ double ss[256];
    __shared__ unsigned int s_krem;
    int t = threadIdx.x;
    if (t == 0) s_krem = g_krem;

    unsigned int c = g_h2c[t];
    double s = (double)g_h2s[t];
    sc[t] = c; ss[t] = s;
    __syncthreads();
    unsigned int krem = s_krem;

    for (int off = 1; off < 256; off <<= 1) {
        unsigned int v = (t + off < 256) ? sc[t + off] : 0u;
        double d       = (t + off < 256) ? ss[t + off] : 0.0;
        __syncthreads();
        sc[t] += v; ss[t] += d;
        __syncthreads();
    }

    unsigned int run = sc[t] - c;
    double runs = ss[t] - s;
    if (run < krem && run + c >= krem) {
        unsigned int ties = krem - run;
        float pivot = __uint_as_float((g_bin0 << 20) | (g_bin1 << 8) | (unsigned int)t);
        double total = g_above + runs + (double)ties * (double)pivot;
        double bce = total / (double)k;
        double sp = (double)g_sum_p, spt = (double)g_sum_pt, stt = (double)g_sum_t;
        double dice = (2.0 * spt + 1e-6) / (sp + stt + 1e-6);
        out[0] = (float)(bce + 0.5 * (1.0 - dice));
    }
}

// ---------------------------------------------------------------------------
extern "C" void kernel_launch(void* const* d_in, const int* in_sizes, int n_in,
                              void* d_out, int out_size) {
    const float* logits  = (const float*)d_in[0];
    const float* targets = (const float*)d_in[1];
    float* out = (float*)d_out;
    int n = in_sizes[0];
    int k = (int)((double)n * 0.2);
    if (k < 1) k = 1;
    int n4 = n / 4;

    zero_all<<<4, 1024>>>((unsigned int)k);
    pass_a<<<1024, 256>>>((const float4*)logits, (const float4*)targets,
                          logits, targets, n4, n);
    select12<0><<<1, 1024>>>();
    pass_b<<<512, 256>>>(n4, n);
    select12<1><<<1, 1024>>>();
    hist2_k<<<256, 256>>>();
    select_final<<<1, 256>>>(out, k);
}

// round 3
// speedup vs baseline: 5.4810x; 5.4810x over previous
#include <cuda_runtime.h>
#include <math.h>

// ============================================================================
// BlobRegressionLoss: mean(top-k BCE) + 0.5 * soft-dice-loss, n = 9,437,184
//
// Exact-rank top-k via sample-guided window select:
//   pass_a : loss keys (fp32 bit patterns, order-preserving for x>=0) + dice
//            sums + 1/16-sampled 4096-bin count histogram (high 12 bits).
//   select : locate pivot high-bin from sample (+-1 at ~80 sigma), 3-bin window.
//   pass_c : exact count+sum of keys ABOVE window (registers, no atomics);
//            keys INSIDE window -> one packed 64-bit smem atomic each into a
//            768-bin fine histogram (20-bit prefix resolution).
//   final  : suffix-scan fine bins; exact rank; low-12-bit ties at bin
//            midpoint (<= 3e-7 relative error). Emits scalar.
// ============================================================================

#define MAX_N 9437184
#define WB    3                 // window width in high-12 bins
#define WBINS (WB * 256)        // fine bins (8 more mantissa bits)
#define FIXS  16384.0f          // fixed-point scale 2^14

__device__ unsigned int g_keys[MAX_N];
__device__ unsigned int g_samp[4096];
__device__ unsigned long long g_w[WBINS];   // (count<<40) | fixed_sum
__device__ float  g_sum_p, g_sum_pt, g_sum_t;
__device__ double g_above;        // exact sum of losses strictly above window
__device__ unsigned int g_cabove; // exact count strictly above window
__device__ int g_wbase;           // window base high-bin

// ---------------------------------------------------------------------------
__global__ void zero_all() {
    int i = blockIdx.x * blockDim.x + threadIdx.x;
    if (i < 4096) g_samp[i] = 0u;
    if (i < WBINS) g_w[i] = 0ULL;
    if (i == 0) {
        g_sum_p = 0.0f; g_sum_pt = 0.0f; g_sum_t = 0.0f;
        g_above = 0.0; g_cabove = 0u; g_wbase = 0;
    }
}

// ---------------------------------------------------------------------------
__device__ __forceinline__ float block_reduce_f(float v, float* sh) {
    int lane = threadIdx.x & 31, wid = threadIdx.x >> 5;
    #pragma unroll
    for (int o = 16; o; o >>= 1) v += __shfl_down_sync(0xffffffffu, v, o);
    if (lane == 0) sh[wid] = v;
    __syncthreads();
    v = (threadIdx.x < (blockDim.x >> 5)) ? sh[threadIdx.x] : 0.0f;
    if (wid == 0) {
        #pragma unroll
        for (int o = 16; o; o >>= 1) v += __shfl_down_sync(0xffffffffu, v, o);
    }
    return v;
}

__device__ __forceinline__ double block_reduce_d(double v, double* sh) {
    int lane = threadIdx.x & 31, wid = threadIdx.x >> 5;
    #pragma unroll
    for (int o = 16; o; o >>= 1) v += __shfl_down_sync(0xffffffffu, v, o);
    if (lane == 0) sh[wid] = v;
    __syncthreads();
    v = (threadIdx.x < (blockDim.x >> 5)) ? sh[threadIdx.x] : 0.0;
    if (wid == 0) {
        #pragma unroll
        for (int o = 16; o; o >>= 1) v += __shfl_down_sync(0xffffffffu, v, o);
    }
    return v;
}

// Fast BCE loss + dice partials (fp32, MUFU intrinsics).
__device__ __forceinline__ unsigned int loss_key(float x, float t,
                                                 float& sp, float& spt, float& st) {
    float ax = fabsf(x);
    float e  = __expf(-ax);
    float loss = fmaxf(x, 0.0f) - x * t + __logf(1.0f + e);
    float inv = __fdividef(1.0f, 1.0f + e);
    float p   = (x >= 0.0f) ? inv : (e * inv);
    sp  += p;
    spt += p * t;
    st  += t;
    return __float_as_uint(loss);
}

// ---------------------------------------------------------------------------
// Pass A: loss keys out, dice sums, 1/16-sampled high-12 count histogram.
__global__ void pass_a(const float4* __restrict__ x4, const float4* __restrict__ t4,
                       const float* __restrict__ x1, const float* __restrict__ t1,
                       int n4, int n) {
    __shared__ unsigned int sh[4096];
    __shared__ float shr[32];
    for (int i = threadIdx.x; i < 4096; i += blockDim.x) sh[i] = 0u;
    __syncthreads();

    float sp = 0.0f, spt = 0.0f, st = 0.0f;
    int tid = blockIdx.x * blockDim.x + threadIdx.x;
    int stride = gridDim.x * blockDim.x;
    uint4* keys4 = reinterpret_cast<uint4*>(g_keys);

    int it = 0;
    for (int i = tid; i < n4; i += stride, it++) {
        float4 xv = x4[i];
        float4 tv = t4[i];
        uint4 kk;
        kk.x = loss_key(xv.x, tv.x, sp, spt, st);
        kk.y = loss_key(xv.y, tv.y, sp, spt, st);
        kk.z = loss_key(xv.z, tv.z, sp, spt, st);
        kk.w = loss_key(xv.w, tv.w, sp, spt, st);
        keys4[i] = kk;
        if ((it & 3) == 0) atomicAdd(&sh[kk.x >> 20], 1u);   // 1/16 sample
    }
    int base = n4 * 4;
    int rem = n - base;
    if (tid < rem) {
        unsigned int key = loss_key(x1[base + tid], t1[base + tid], sp, spt, st);
        g_keys[base + tid] = key;
    }
    __syncthreads();

    for (int i = threadIdx.x; i < 4096; i += blockDim.x) {
        unsigned int c = sh[i];
        if (c) atomicAdd(&g_samp[i], c);
    }

    float r = block_reduce_f(sp, shr);
    if (threadIdx.x == 0) atomicAdd(&g_sum_p, r);
    __syncthreads();
    r = block_reduce_f(spt, shr);
    if (threadIdx.x == 0) atomicAdd(&g_sum_pt, r);
    __syncthreads();
    r = block_reduce_f(st, shr);
    if (threadIdx.x == 0) atomicAdd(&g_sum_t, r);
}

// ---------------------------------------------------------------------------
// Sample select: find the high-12 bin where the sampled rank crosses k/16,
// set the 3-bin window base (crossing bin - 1, clamped).
__global__ void select_s(unsigned int kk16) {
    __shared__ unsigned int sc[1024];
    int t = threadIdx.x;
    unsigned int h[4];
    unsigned int local = 0;
    #pragma unroll
    for (int j = 0; j < 4; j++) { h[j] = g_samp[t * 4 + j]; local += h[j]; }
    sc[t] = local;
    __syncthreads();

    for (int off = 1; off < 1024; off <<= 1) {
        unsigned int v = (t + off < 1024) ? sc[t + off] : 0u;
        __syncthreads();
        sc[t] += v;
        __syncthreads();
    }

    unsigned int run = sc[t] - local;   // samples strictly above my chunk
    for (int j = 3; j >= 0; j--) {
        unsigned int c = h[j];
        if (run < kk16 && run + c >= kk16) {
            int b = t * 4 + j - 1;
            if (b < 0) b = 0;
            if (b > 4096 - WB) b = 4096 - WB;
            g_wbase = b;
        }
        run += c;
    }
}

// ---------------------------------------------------------------------------
// Pass C: exact stats. Above window -> register count+sum. In window -> one
// packed 64-bit smem atomic into 768-bin fine hist (bits 19:12 within window).
__global__ void pass_c(int n4, int n) {
    __shared__ unsigned long long shw[WBINS];
    __shared__ double shd[32];
    for (int i = threadIdx.x; i < WBINS; i += blockDim.x) shw[i] = 0ULL;
    __syncthreads();

    unsigned int wbase = (unsigned int)g_wbase;
    unsigned int lo = wbase << 20;
    unsigned int hi = (wbase + WB) << 20;
    unsigned int sub = wbase << 8;

    double sd = 0.0;
    unsigned int cab = 0;
    int tid = blockIdx.x * blockDim.x + threadIdx.x;
    int stride = gridDim.x * blockDim.x;
    const uint4* keys4 = reinterpret_cast<const uint4*>(g_keys);

    for (int i = tid; i < n4; i += stride) {
        uint4 kk = keys4[i];
        unsigned int ks[4] = {kk.x, kk.y, kk.z, kk.w};
        float sf = 0.0f;
        #pragma unroll
        for (int j = 0; j < 4; j++) {
            unsigned int key = ks[j];
            if (key >= hi) {
                sf += __uint_as_float(key);
                cab++;
            } else if (key >= lo) {
                unsigned int bin = (key >> 12) - sub;     // 0..WBINS-1
                unsigned long long contrib = (1ULL << 40) |
                    (unsigned long long)__float2uint_rn(__uint_as_float(key) * FIXS);
                atomicAdd(&shw[bin], contrib);
            }
        }
        sd += (double)sf;
    }
    int base = n4 * 4;
    int rem = n - base;
    if (tid < rem) {
        unsigned int key = g_keys[base + tid];
        if (key >= hi) { sd += (double)__uint_as_float(key); cab++; }
        else if (key >= lo) {
            unsigned int bin = (key >> 12) - sub;
            unsigned long long contrib = (1ULL << 40) |
                (unsigned long long)__float2uint_rn(__uint_as_float(key) * FIXS);
            atomicAdd(&shw[bin], contrib);
        }
    }
    __syncthreads();

    for (int i = threadIdx.x; i < WBINS; i += blockDim.x) {
        unsigned long long v = shw[i];
        if (v) atomicAdd(&g_w[i], v);
    }

    double rd = block_reduce_d(sd, shd);
    if (threadIdx.x == 0) atomicAdd(&g_above, rd);
    __syncthreads();
    // reuse shd for count reduction (as double; counts are small exact ints)
    double rc = block_reduce_d((double)cab, shd);
    if (threadIdx.x == 0) atomicAdd(&g_cabove, (unsigned int)(rc + 0.5));
}

// ---------------------------------------------------------------------------
// Final: suffix-scan 768 fine bins, exact rank, ties at 20-bit-bin midpoint.
__global__ void select_final(float* out, int k) {
    __shared__ unsigned int sc[256];
    __shared__ double ss[256];
    int t = threadIdx.x;

    unsigned int h[WB]; double hs[WB];
    unsigned int local = 0; double lsum = 0.0;
    #pragma unroll
    for (int j = 0; j < WB; j++) {
        unsigned long long v = g_w[t * WB + j];
        h[j] = (unsigned int)(v >> 40);
        hs[j] = (double)(v & ((1ULL << 40) - 1ULL)) * (1.0 / (double)FIXS);
        local += h[j]; lsum += hs[j];
    }
    sc[t] = local; ss[t] = lsum;
    __syncthreads();

    for (int off = 1; off < 256; off <<= 1) {
        unsigned int v = (t + off < 256) ? sc[t + off] : 0u;
        double d       = (t + off < 256) ? ss[t + off] : 0.0;
        __syncthreads();
        sc[t] += v; ss[t] += d;
        __syncthreads();
    }

    unsigned int cab = g_cabove;
    long long krem_ll = (long long)k - (long long)cab;
    unsigned int wbase = (unsigned int)g_wbase;

    if (krem_ll > 0) {
        unsigned int krem = (unsigned int)krem_ll;
        unsigned int run = sc[t] - local;   // in-window count strictly above my chunk
        double runs = ss[t] - lsum;
        for (int j = WB - 1; j >= 0; j--) {
            unsigned int c = h[j];
            if (run < krem && run + c >= krem) {
                unsigned int ties = krem - run;
                int fb = t * WB + j;
                unsigned int key_mid = (wbase << 20) + ((unsigned int)fb << 12) + 0x800u;
                double mid = (double)__uint_as_float(key_mid);
                double total = g_above + runs + (double)ties * mid;
                double bce = total / (double)k;
                double sp = (double)g_sum_p, spt = (double)g_sum_pt, stt = (double)g_sum_t;
                double dice = (2.0 * spt + 1e-6) / (sp + stt + 1e-6);
                out[0] = (float)(bce + 0.5 * (1.0 - dice));
            }
            run += c;
            runs += hs[j];
        }
    } else if (t == 0) {
        // Sampling-window fallback (statistically unreachable): approximate
        // with everything above the window.
        double bce = g_above / (double)(cab ? cab : 1u);
        double sp = (double)g_sum_p, spt = (double)g_sum_pt, stt = (double)g_sum_t;
        double dice = (2.0 * spt + 1e-6) / (sp + stt + 1e-6);
        out[0] = (float)(bce + 0.5 * (1.0 - dice));
    }
}

// ---------------------------------------------------------------------------
extern "C" void kernel_launch(void* const* d_in, const int* in_sizes, int n_in,
                              void* d_out, int out_size) {
    const float* logits  = (const float*)d_in[0];
    const float* targets = (const float*)d_in[1];
    float* out = (float*)d_out;
    int n = in_sizes[0];
    int k = (int)((double)n * 0.2);
    if (k < 1) k = 1;
    int n4 = n / 4;
    unsigned int kk16 = (unsigned int)(k / 16);
    if (kk16 < 1) kk16 = 1;

    zero_all<<<8, 1024>>>();
    pass_a<<<1024, 256>>>((const float4*)logits, (const float4*)targets,
                          logits, targets, n4, n);
    select_s<<<1, 1024>>>(kk16);
    pass_c<<<1024, 256>>>(n4, n);
    select_final<<<1, 256>>>(out, k);
}

// round 5
// speedup vs baseline: 6.7681x; 1.2348x over previous
#include <cuda_runtime.h>
#include <cuda_bf16.h>
#include <math.h>

// ============================================================================
// BlobRegressionLoss: mean(top-k BCE) + 0.5 * soft-dice-loss, n = 9,437,184
//
// bf16-key sample-guided exact select:
//   pass_a : loss -> RN-bf16 key (order-preserving, >=0), 16-bit key store,
//            dice sums, deterministically sampled 4096-bin hist of key>>4.
//            2 MUFU/elem (exp, log); sigmoid reciprocal via range-reduced
//            Newton (D = u/2 in (0.5,1], seed 48/17 - 32/17*D, 2 steps).
//   select : sampled suffix-scan locates pivot bin (threshold matches the
//            ACTUAL sample fraction, computed host-side); 3-bin window.
//   pass_c : re-read 16-bit keys (19MB). Above window: register count+sum.
//            In window: only 48 distinct bf16 values -> count-only histogram
//            with __match_any_sync warp aggregation (sum == count * value).
//   final  : 48-bin walk, exact rank & tie handling at bf16 granularity.
// ============================================================================

#define MAX_N 9437184
#define WB    3                   // window width in (key>>4) bins
#define FBINS (WB * 16)           // 48 distinct bf16 keys in window

__device__ unsigned short g_keys16[MAX_N];
__device__ unsigned int g_samp[4096];
__device__ unsigned int g_fine[FBINS];
__device__ float  g_sum_p, g_sum_pt, g_sum_t;
__device__ double g_above;          // exact sum of losses strictly above window
__device__ unsigned int g_cabove;   // exact count strictly above window
__device__ int g_wbase;             // window base (key>>4 bin)

// ---------------------------------------------------------------------------
__global__ void zero_all() {
    int i = blockIdx.x * blockDim.x + threadIdx.x;
    if (i < 4096) g_samp[i] = 0u;
    if (i < FBINS) g_fine[i] = 0u;
    if (i == 0) {
        g_sum_p = 0.0f; g_sum_pt = 0.0f; g_sum_t = 0.0f;
        g_above = 0.0; g_cabove = 0u; g_wbase = 0;
    }
}

// ---------------------------------------------------------------------------
__device__ __forceinline__ float block_reduce_f(float v, float* sh) {
    int lane = threadIdx.x & 31, wid = threadIdx.x >> 5;
    #pragma unroll
    for (int o = 16; o; o >>= 1) v += __shfl_down_sync(0xffffffffu, v, o);
    if (lane == 0) sh[wid] = v;
    __syncthreads();
    v = (threadIdx.x < (blockDim.x >> 5)) ? sh[threadIdx.x] : 0.0f;
    if (wid == 0) {
        #pragma unroll
        for (int o = 16; o; o >>= 1) v += __shfl_down_sync(0xffffffffu, v, o);
    }
    return v;
}

__device__ __forceinline__ double block_reduce_d(double v, double* sh) {
    int lane = threadIdx.x & 31, wid = threadIdx.x >> 5;
    #pragma unroll
    for (int o = 16; o; o >>= 1) v += __shfl_down_sync(0xffffffffu, v, o);
    if (lane == 0) sh[wid] = v;
    __syncthreads();
    v = (threadIdx.x < (blockDim.x >> 5)) ? sh[threadIdx.x] : 0.0;
    if (wid == 0) {
        #pragma unroll
        for (int o = 16; o; o >>= 1) v += __shfl_down_sync(0xffffffffu, v, o);
    }
    return v;
}

// BCE loss key (bf16 RN bits) + dice partials. 2 MUFU (ex2, lg2) + FMA rcp.
__device__ __forceinline__ unsigned int loss_key16(float x, float t,
                                                   float& sp, float& spt, float& st) {
    float ax = fabsf(x);
    float e  = __expf(-ax);                   // MUFU ex2
    float u  = 1.0f + e;                      // u in (1, 2]
    float lg = __logf(u);                     // MUFU lg2 : log1p(e)
    float loss = fmaxf(x, 0.0f) - x * t + lg;
    // 1/u via Newton on D = u/2 in (0.5, 1]: seed 48/17 - 32/17*D (valid range),
    // two steps -> rel err <= 1.2e-5. 1/u = r/2. FMA pipe only.
    float D = 0.5f * u;
    float r = 2.82352941f - 1.88235294f * D;
    r = r * (2.0f - D * r);
    r = r * (2.0f - D * r);
    float invu = 0.5f * r;
    float p = (x >= 0.0f) ? invu : (e * invu);   // sigmoid(x)
    sp  += p;
    spt += p * t;
    st  += t;
    __nv_bfloat16 b = __float2bfloat16(loss);    // RN
    return (unsigned int)__bfloat16_as_ushort(b);
}

// ---------------------------------------------------------------------------
// Pass A: 16-bit keys out, dice sums, sampled high-12 count histogram
// (first key of every 4th grid-stride float4 iteration).
__global__ void pass_a(const float4* __restrict__ x4, const float4* __restrict__ t4,
                       const float* __restrict__ x1, const float* __restrict__ t1,
                       int n4, int n) {
    __shared__ unsigned int sh[4096];
    __shared__ float shr[32];
    for (int i = threadIdx.x; i < 4096; i += blockDim.x) sh[i] = 0u;
    __syncthreads();

    float sp = 0.0f, spt = 0.0f, st = 0.0f;
    int tid = blockIdx.x * blockDim.x + threadIdx.x;
    int stride = gridDim.x * blockDim.x;
    uint2* keys2 = reinterpret_cast<uint2*>(g_keys16);  // 4 keys per uint2

    int it = 0;
    for (int i = tid; i < n4; i += stride, it++) {
        float4 xv = x4[i];
        float4 tv = t4[i];
        unsigned int k0 = loss_key16(xv.x, tv.x, sp, spt, st);
        unsigned int k1 = loss_key16(xv.y, tv.y, sp, spt, st);
        unsigned int k2 = loss_key16(xv.z, tv.z, sp, spt, st);
        unsigned int k3 = loss_key16(xv.w, tv.w, sp, spt, st);
        uint2 pk;
        pk.x = k0 | (k1 << 16);
        pk.y = k2 | (k3 << 16);
        keys2[i] = pk;
        if ((it & 3) == 0) atomicAdd(&sh[k0 >> 4], 1u);
    }
    int base = n4 * 4;
    int rem = n - base;
    if (tid < rem) {
        unsigned int key = loss_key16(x1[base + tid], t1[base + tid], sp, spt, st);
        g_keys16[base + tid] = (unsigned short)key;
    }
    __syncthreads();

    for (int i = threadIdx.x; i < 4096; i += blockDim.x) {
        unsigned int c = sh[i];
        if (c) atomicAdd(&g_samp[i], c);
    }

    float r = block_reduce_f(sp, shr);
    if (threadIdx.x == 0) atomicAdd(&g_sum_p, r);
    __syncthreads();
    r = block_reduce_f(spt, shr);
    if (threadIdx.x == 0) atomicAdd(&g_sum_pt, r);
    __syncthreads();
    r = block_reduce_f(st, shr);
    if (threadIdx.x == 0) atomicAdd(&g_sum_t, r);
}

// ---------------------------------------------------------------------------
// Sample select: find crossing bin of sampled rank ksamp -> window base (bin-1).
__global__ void select_s(unsigned int ksamp) {
    __shared__ unsigned int sc[1024];
    int t = threadIdx.x;
    unsigned int h[4];
    unsigned int local = 0;
    #pragma unroll
    for (int j = 0; j < 4; j++) { h[j] = g_samp[t * 4 + j]; local += h[j]; }
    sc[t] = local;
    __syncthreads();

    for (int off = 1; off < 1024; off <<= 1) {
        unsigned int v = (t + off < 1024) ? sc[t + off] : 0u;
        __syncthreads();
        sc[t] += v;
        __syncthreads();
    }

    unsigned int run = sc[t] - local;
    for (int j = 3; j >= 0; j--) {
        unsigned int c = h[j];
        if (run < ksamp && run + c >= ksamp) {
            int b = t * 4 + j - 1;
            if (b < 0) b = 0;
            if (b > 4096 - WB) b = 4096 - WB;
            g_wbase = b;
        }
        run += c;
    }
}

// ---------------------------------------------------------------------------
// Pass C: above window -> register count+sum; in window -> count-only 48-bin
// histogram with match_any warp aggregation (all elems in a bin share a value).
__global__ void pass_c(int n8, int n) {
    __shared__ unsigned int shc[FBINS];
    __shared__ double shd[32];
    __shared__ unsigned int shu[32];
    if (threadIdx.x < FBINS) shc[threadIdx.x] = 0u;
    __syncthreads();

    int lo16 = g_wbase << 4;
    int hi16 = lo16 + FBINS;

    float sf = 0.0f;
    double sd = 0.0;
    unsigned int cab = 0;
    int lane = threadIdx.x & 31;
    int tid = blockIdx.x * blockDim.x + threadIdx.x;
    int stride = gridDim.x * blockDim.x;
    const uint4* keys8 = reinterpret_cast<const uint4*>(g_keys16);

    int iters = (n8 + stride - 1) / stride;
    for (int itr = 0; itr < iters; itr++) {
        int i = tid + itr * stride;
        bool in = (i < n8);
        uint4 kk = in ? keys8[i] : make_uint4(0u, 0u, 0u, 0u);
        unsigned int w[4] = {kk.x, kk.y, kk.z, kk.w};
        #pragma unroll
        for (int j = 0; j < 4; j++) {
            #pragma unroll
            for (int h = 0; h < 2; h++) {
                int key = (int)((w[j] >> (h * 16)) & 0xFFFFu);
                bool above = in && (key >= hi16);
                bool inw   = in && !above && (key >= lo16);
                if (above) {
                    sf += __uint_as_float(((unsigned int)key) << 16);
                    cab++;
                }
                unsigned int m = __ballot_sync(0xffffffffu, inw);
                if (inw) {
                    int bin = key - lo16;
                    unsigned int grp = __match_any_sync(m, bin);
                    int leader = __ffs(grp) - 1;
                    if (lane == leader) atomicAdd(&shc[bin], (unsigned int)__popc(grp));
                }
            }
        }
        sd += (double)sf;       // drain fp32 partial each iter into fp64
        sf = 0.0f;
    }
    int base = n8 * 8;
    int tix = base + tid;
    if (tix < n) {
        int key = (int)g_keys16[tix];
        if (key >= hi16) { sd += (double)__uint_as_float(((unsigned int)key) << 16); cab++; }
        else if (key >= lo16) atomicAdd(&shc[key - lo16], 1u);
    }
    __syncthreads();

    if (threadIdx.x < FBINS) {
        unsigned int c = shc[threadIdx.x];
        if (c) atomicAdd(&g_fine[threadIdx.x], c);
    }

    double rd = block_reduce_d(sd, shd);
    if (threadIdx.x == 0) atomicAdd(&g_above, rd);
    __syncthreads();
    {
        unsigned int v = cab;
        #pragma unroll
        for (int o = 16; o; o >>= 1) v += __shfl_down_sync(0xffffffffu, v, o);
        if (lane == 0) shu[threadIdx.x >> 5] = v;
        __syncthreads();
        if (threadIdx.x < 32) {
            unsigned int x = (threadIdx.x < (blockDim.x >> 5)) ? shu[threadIdx.x] : 0u;
            #pragma unroll
            for (int o = 16; o; o >>= 1) x += __shfl_down_sync(0xffffffffu, x, o);
            if (threadIdx.x == 0 && x) atomicAdd(&g_cabove, x);
        }
    }
}

// ---------------------------------------------------------------------------
// Final: walk 48 bins top-down; exact rank; ties exact (shared bf16 value).
__global__ void select_final(float* out, int k) {
    unsigned int cab = g_cabove;
    double total = g_above;
    long long krem = (long long)k - (long long)cab;
    int wbase = g_wbase;

    if (krem > 0) {
        unsigned int run = 0;
        for (int fb = FBINS - 1; fb >= 0; fb--) {
            unsigned int c = g_fine[fb];
            double v = (double)__uint_as_float(((unsigned int)((wbase << 4) + fb)) << 16);
            if ((long long)(run + c) >= krem) {
                unsigned int ties = (unsigned int)krem - run;
                total += (double)ties * v;
                break;
            }
            run += c;
            total += (double)c * v;
        }
    }
    double bce = total / (double)k;
    double sp = (double)g_sum_p, spt = (double)g_sum_pt, stt = (double)g_sum_t;
    double dice = (2.0 * spt + 1e-6) / (sp + stt + 1e-6);
    out[0] = (float)(bce + 0.5 * (1.0 - dice));
}

// ---------------------------------------------------------------------------
extern "C" void kernel_launch(void* const* d_in, const int* in_sizes, int n_in,
                              void* d_out, int out_size) {
    const float* logits  = (const float*)d_in[0];
    const float* targets = (const float*)d_in[1];
    float* out = (float*)d_out;
    int n = in_sizes[0];
    int k = (int)((double)n * 0.2);
    if (k < 1) k = 1;
    int n4 = n / 4;
    int n8 = n / 8;

    const int BLOCKS = 1024, THREADS = 256;
    // Actual sampled count: every 4th grid-stride iteration contributes one
    // key per thread (only threads whose index is in range; exact when
    // n4 % stride == 0, close otherwise).
    long long stride = (long long)BLOCKS * THREADS;
    long long iters = (n4 + stride - 1) / stride;
    long long sampled_iters = (iters + 3) / 4;
    long long samples = sampled_iters * stride;
    if (samples > n4) samples = n4;
    unsigned int ksamp = (unsigned int)(((double)k * (double)samples) / (double)n);
    if (ksamp < 1) ksamp = 1;

    zero_all<<<4, 1024>>>();
    pass_a<<<BLOCKS, THREADS>>>((const float4*)logits, (const float4*)targets,
                                logits, targets, n4, n);
    select_s<<<1, 1024>>>(ksamp);
    pass_c<<<BLOCKS, THREADS>>>(n8, n);
    select_final<<<1, 1>>>(out, k);
}

// round 6
// speedup vs baseline: 7.5342x; 1.1132x over previous
#include <cuda_runtime.h>
#include <cuda_bf16.h>
#include <math.h>

// ============================================================================
// BlobRegressionLoss: mean(top-k BCE) + 0.5 * soft-dice-loss, n = 9,437,184
//
// bf16-key sample-guided exact select (4 launches, self-cleaning globals):
//   pass_a : loss -> RN-bf16 key (order-preserving, >=0), 16-bit key store,
//            dice sums, sampled 4096-bin hist of key>>4.
//   select_s: sampled suffix-scan locates pivot bin; 3-bin window; zeros hist.
//   pass_c : re-read keys (19MB, L2-resident). Above window: predicated
//            register sum. In window: lane-replicated 48x32 count histogram
//            (sum == count * value, values exact at bf16 granularity).
//   select_final: 48-bin walk, exact rank & ties; emits scalar; zeros state.
// ============================================================================

#define MAX_N 9437184
#define WB    3                   // window width in (key>>4) bins
#define FBINS (WB * 16)           // 48 distinct bf16 keys in window

__device__ unsigned short g_keys16[MAX_N];
__device__ unsigned int g_samp[4096];
__device__ unsigned int g_fine[FBINS];
__device__ float  g_sum_p, g_sum_pt, g_sum_t;
__device__ double g_above;          // exact sum of losses strictly above window
__device__ unsigned int g_cabove;   // exact count strictly above window
__device__ int g_wbase;             // window base (key>>4 bin)

// ---------------------------------------------------------------------------
__device__ __forceinline__ float block_reduce_f(float v, float* sh) {
    int lane = threadIdx.x & 31, wid = threadIdx.x >> 5;
    #pragma unroll
    for (int o = 16; o; o >>= 1) v += __shfl_down_sync(0xffffffffu, v, o);
    if (lane == 0) sh[wid] = v;
    __syncthreads();
    v = (threadIdx.x < (blockDim.x >> 5)) ? sh[threadIdx.x] : 0.0f;
    if (wid == 0) {
        #pragma unroll
        for (int o = 16; o; o >>= 1) v += __shfl_down_sync(0xffffffffu, v, o);
    }
    return v;
}

__device__ __forceinline__ double block_reduce_d(double v, double* sh) {
    int lane = threadIdx.x & 31, wid = threadIdx.x >> 5;
    #pragma unroll
    for (int o = 16; o; o >>= 1) v += __shfl_down_sync(0xffffffffu, v, o);
    if (lane == 0) sh[wid] = v;
    __syncthreads();
    v = (threadIdx.x < (blockDim.x >> 5)) ? sh[threadIdx.x] : 0.0;
    if (wid == 0) {
        #pragma unroll
        for (int o = 16; o; o >>= 1) v += __shfl_down_sync(0xffffffffu, v, o);
    }
    return v;
}

// BCE loss key (bf16 RN bits) + dice partials. 2 MUFU (ex2, lg2) + FMA rcp.
__device__ __forceinline__ unsigned int loss_key16(float x, float t,
                                                   float& sp, float& spt, float& st) {
    float ax = fabsf(x);
    float e  = __expf(-ax);                   // MUFU ex2
    float u  = 1.0f + e;                      // u in (1, 2]
    float lg = __logf(u);                     // MUFU lg2 : log1p(e)
    float loss = fmaxf(x, 0.0f) - x * t + lg;
    // 1/u via Newton on D = u/2 in (0.5, 1]: seed valid on this range,
    // two steps -> rel err <= 1.2e-5. 1/u = r/2. FMA pipe only.
    float D = 0.5f * u;
    float r = 2.82352941f - 1.88235294f * D;
    r = r * (2.0f - D * r);
    r = r * (2.0f - D * r);
    float invu = 0.5f * r;
    float p = (x >= 0.0f) ? invu : (e * invu);   // sigmoid(x)
    sp  += p;
    spt += p * t;
    st  += t;
    __nv_bfloat16 b = __float2bfloat16(loss);    // RN
    return (unsigned int)__bfloat16_as_ushort(b);
}

// ---------------------------------------------------------------------------
// Pass A: 16-bit keys out, dice sums, sampled high-12 count histogram
// (first key of every 4th grid-stride float4 iteration).
__global__ void pass_a(const float4* __restrict__ x4, const float4* __restrict__ t4,
                       const float* __restrict__ x1, const float* __restrict__ t1,
                       int n4, int n) {
    __shared__ unsigned int sh[4096];
    __shared__ float shr[32];
    for (int i = threadIdx.x; i < 4096; i += blockDim.x) sh[i] = 0u;
    __syncthreads();

    float sp = 0.0f, spt = 0.0f, st = 0.0f;
    int tid = blockIdx.x * blockDim.x + threadIdx.x;
    int stride = gridDim.x * blockDim.x;
    uint2* keys2 = reinterpret_cast<uint2*>(g_keys16);  // 4 keys per uint2

    int it = 0;
    for (int i = tid; i < n4; i += stride, it++) {
        float4 xv = x4[i];
        float4 tv = t4[i];
        unsigned int k0 = loss_key16(xv.x, tv.x, sp, spt, st);
        unsigned int k1 = loss_key16(xv.y, tv.y, sp, spt, st);
        unsigned int k2 = loss_key16(xv.z, tv.z, sp, spt, st);
        unsigned int k3 = loss_key16(xv.w, tv.w, sp, spt, st);
        uint2 pk;
        pk.x = k0 | (k1 << 16);
        pk.y = k2 | (k3 << 16);
        keys2[i] = pk;
        if ((it & 3) == 0) atomicAdd(&sh[k0 >> 4], 1u);
    }
    int base = n4 * 4;
    int rem = n - base;
    if (tid < rem) {
        unsigned int key = loss_key16(x1[base + tid], t1[base + tid], sp, spt, st);
        g_keys16[base + tid] = (unsigned short)key;
    }
    __syncthreads();

    for (int i = threadIdx.x; i < 4096; i += blockDim.x) {
        unsigned int c = sh[i];
        if (c) atomicAdd(&g_samp[i], c);
    }

    float r = block_reduce_f(sp, shr);
    if (threadIdx.x == 0) atomicAdd(&g_sum_p, r);
    __syncthreads();
    r = block_reduce_f(spt, shr);
    if (threadIdx.x == 0) atomicAdd(&g_sum_pt, r);
    __syncthreads();
    r = block_reduce_f(st, shr);
    if (threadIdx.x == 0) atomicAdd(&g_sum_t, r);
}

// ---------------------------------------------------------------------------
// Sample select: crossing bin of sampled rank ksamp -> window base (bin-1).
// Also zeros g_samp for the next graph replay (self-cleaning).
__global__ void select_s(unsigned int ksamp) {
    __shared__ unsigned int sc[1024];
    int t = threadIdx.x;
    unsigned int h[4];
    unsigned int local = 0;
    #pragma unroll
    for (int j = 0; j < 4; j++) {
        h[j] = g_samp[t * 4 + j];
        g_samp[t * 4 + j] = 0u;     // self-clean (each bin read only by owner)
        local += h[j];
    }
    sc[t] = local;
    __syncthreads();

    for (int off = 1; off < 1024; off <<= 1) {
        unsigned int v = (t + off < 1024) ? sc[t + off] : 0u;
        __syncthreads();
        sc[t] += v;
        __syncthreads();
    }

    unsigned int run = sc[t] - local;
    for (int j = 3; j >= 0; j--) {
        unsigned int c = h[j];
        if (run < ksamp && run + c >= ksamp) {
            int b = t * 4 + j - 1;
            if (b < 0) b = 0;
            if (b > 4096 - WB) b = 4096 - WB;
            g_wbase = b;
        }
        run += c;
    }
}

// ---------------------------------------------------------------------------
// Pass C: above window -> predicated register sum; in window -> lane-replicated
// 48x32 count-only histogram (no ballots/matches; spread-address smem atomics).
__global__ void pass_c(int n8, int n) {
    __shared__ unsigned int shc[FBINS * 32];
    __shared__ double shd[32];
    __shared__ unsigned int shu[32];
    for (int i = threadIdx.x; i < FBINS * 32; i += blockDim.x) shc[i] = 0u;
    __syncthreads();

    unsigned int lo16 = (unsigned int)(g_wbase << 4);
    unsigned int hi16 = lo16 + FBINS;
    int lane = threadIdx.x & 31;

    double sd = 0.0;
    unsigned int cab = 0;
    int tid = blockIdx.x * blockDim.x + threadIdx.x;
    int stride = gridDim.x * blockDim.x;
    const uint4* keys8 = reinterpret_cast<const uint4*>(g_keys16);

    #pragma unroll 2
    for (int i = tid; i < n8; i += stride) {
        uint4 kk = keys8[i];
        unsigned int w[4] = {kk.x, kk.y, kk.z, kk.w};
        float sf = 0.0f;
        #pragma unroll
        for (int j = 0; j < 4; j++) {
            unsigned int klo = w[j] & 0xFFFFu;
            unsigned int khi = w[j] >> 16;
            unsigned int dlo = klo - lo16;      // unsigned wrap if below window
            unsigned int dhi = khi - lo16;
            if (dlo < FBINS) atomicAdd(&shc[(dlo << 5) + lane], 1u);
            else if (klo >= hi16) { sf += __uint_as_float(klo << 16); cab++; }
            if (dhi < FBINS) atomicAdd(&shc[(dhi << 5) + lane], 1u);
            else if (khi >= hi16) { sf += __uint_as_float(khi << 16); cab++; }
        }
        sd += (double)sf;                       // drain fp32 partial each iter
    }
    // scalar tail
    int base = n8 * 8;
    int tix = base + tid;
    if (tix < n) {
        unsigned int key = (unsigned int)g_keys16[tix];
        unsigned int d = key - lo16;
        if (d < FBINS) atomicAdd(&shc[(d << 5) + lane], 1u);
        else if (key >= hi16) { sd += (double)__uint_as_float(key << 16); cab++; }
    }
    __syncthreads();

    // flush lane-replicated histogram
    for (int b = threadIdx.x; b < FBINS; b += blockDim.x) {
        unsigned int s = 0;
        #pragma unroll
        for (int l = 0; l < 32; l++) s += shc[(b << 5) + l];
        if (s) atomicAdd(&g_fine[b], s);
    }

    double rd = block_reduce_d(sd, shd);
    if (threadIdx.x == 0) atomicAdd(&g_above, rd);
    __syncthreads();
    {
        unsigned int v = cab;
        #pragma unroll
        for (int o = 16; o; o >>= 1) v += __shfl_down_sync(0xffffffffu, v, o);
        if (lane == 0) shu[threadIdx.x >> 5] = v;
        __syncthreads();
        if (threadIdx.x < 32) {
            unsigned int x = (threadIdx.x < (blockDim.x >> 5)) ? shu[threadIdx.x] : 0u;
            #pragma unroll
            for (int o = 16; o; o >>= 1) x += __shfl_down_sync(0xffffffffu, x, o);
            if (threadIdx.x == 0 && x) atomicAdd(&g_cabove, x);
        }
    }
}

// ---------------------------------------------------------------------------
// Final: walk 48 bins top-down; exact rank; ties exact (shared bf16 value).
// Self-cleans all accumulators for the next graph replay.
__global__ void select_final(float* out, int k) {
    unsigned int cab = g_cabove;
    double total = g_above;
    float sp_f = g_sum_p, spt_f = g_sum_pt, st_f = g_sum_t;
    long long krem = (long long)k - (long long)cab;
    int wbase = g_wbase;

    unsigned int fine[FBINS];
    #pragma unroll
    for (int fb = 0; fb < FBINS; fb++) { fine[fb] = g_fine[fb]; g_fine[fb] = 0u; }
    g_above = 0.0; g_cabove = 0u;
    g_sum_p = 0.0f; g_sum_pt = 0.0f; g_sum_t = 0.0f;

    if (krem > 0) {
        unsigned int run = 0;
        for (int fb = FBINS - 1; fb >= 0; fb--) {
            unsigned int c = fine[fb];
            double v = (double)__uint_as_float(((unsigned int)((wbase << 4) + fb)) << 16);
            if ((long long)(run + c) >= krem) {
                unsigned int ties = (unsigned int)krem - run;
                total += (double)ties * v;
                break;
            }
            run += c;
            total += (double)c * v;
        }
    }
    double bce = total / (double)k;
    double sp = (double)sp_f, spt = (double)spt_f, stt = (double)st_f;
    double dice = (2.0 * spt + 1e-6) / (sp + stt + 1e-6);
    out[0] = (float)(bce + 0.5 * (1.0 - dice));
}

// ---------------------------------------------------------------------------
extern "C" void kernel_launch(void* const* d_in, const int* in_sizes, int n_in,
                              void* d_out, int out_size) {
    const float* logits  = (const float*)d_in[0];
    const float* targets = (const float*)d_in[1];
    float* out = (float*)d_out;
    int n = in_sizes[0];
    int k = (int)((double)n * 0.2);
    if (k < 1) k = 1;
    int n4 = n / 4;
    int n8 = n / 8;

    const int BLOCKS = 1024, THREADS = 256;
    // Actual sampled count (first key of every 4th grid-stride iteration).
    long long stride = (long long)BLOCKS * THREADS;
    long long iters = (n4 + stride - 1) / stride;
    long long sampled_iters = (iters + 3) / 4;
    long long samples = sampled_iters * stride;
    if (samples > n4) samples = n4;
    unsigned int ksamp = (unsigned int)(((double)k * (double)samples) / (double)n);
    if (ksamp < 1) ksamp = 1;

    pass_a<<<BLOCKS, THREADS>>>((const float4*)logits, (const float4*)targets,
                                logits, targets, n4, n);
    select_s<<<1, 1024>>>(ksamp);
    pass_c<<<BLOCKS, THREADS>>>(n8, n);
    select_final<<<1, 1>>>(out, k);
}